// round 14
// baseline (speedup 1.0000x reference)
#include <cuda_runtime.h>

#define NN 50000
#define NE 800000
#define HCD 64
#define NTILES 49   // ceil(50000/1024)

// ---------------- scratch (static device globals; allocation-free) ----------
__device__ __align__(16) float g_xs[NN * HCD];      // layer-1 xs
__device__ __align__(16) float g_xs2[NN * HCD];     // layer-2 xs (fused lin2 out)
__device__ __align__(16) float g_acc[NN * HCD];     // layer2 out (pre-pool)
__device__ __align__(16) float g_asrc[NN * 4];      // layer-1 a_src
__device__ __align__(16) float g_adst[NN * 4];      // layer-1 a_dst
__device__ __align__(16) float g_asrc2[NN * 4];     // layer-2 a_src
__device__ __align__(16) float g_adst2[NN * 4];     // layer-2 a_dst
__device__ __align__(16) float g_ce[8];             // [0..3] layer1, [4..7] layer2
// CSR build
__device__ int g_deg[NN];
__device__ int g_start[NN + 1];
__device__ int g_cursor[NN];
__device__ int g_bsum[NTILES];
__device__ __align__(16) int2 g_edge[NE];           // {src, ea bits} in CSR order

// ---------------- helpers ----------------------------------------------------
__device__ __forceinline__ float red16(float v) {
    v += __shfl_xor_sync(0xffffffffu, v, 8);
    v += __shfl_xor_sync(0xffffffffu, v, 4);
    v += __shfl_xor_sync(0xffffffffu, v, 2);
    v += __shfl_xor_sync(0xffffffffu, v, 1);
    return v;
}

// ---------------- hist (8 edges/thread) + fused ce constants -----------------
__global__ void k_hist(const int* __restrict__ ei,
                       const float* __restrict__ We1, const float* __restrict__ ae1,
                       const float* __restrict__ We2, const float* __restrict__ ae2) {
    if (blockIdx.x == 0 && threadIdx.x < 128) {
        int t = threadIdx.x;
        int layer = t >> 6;
        int c = t & 63;
        const float* We = layer ? We2 : We1;
        const float* ae = layer ? ae2 : ae1;
        float v = red16(We[c] * ae[c]);
        if ((c & 15) == 0) g_ce[layer * 4 + (c >> 4)] = v;
    }
    int t = blockIdx.x * blockDim.x + threadIdx.x;
    int e = t * 8;
    if (e >= NE) return;
    int4 d0 = *(const int4*)&ei[NE + e];
    int4 d1 = *(const int4*)&ei[NE + e + 4];
    atomicAdd(&g_deg[d0.x], 1); atomicAdd(&g_deg[d0.y], 1);
    atomicAdd(&g_deg[d0.z], 1); atomicAdd(&g_deg[d0.w], 1);
    atomicAdd(&g_deg[d1.x], 1); atomicAdd(&g_deg[d1.y], 1);
    atomicAdd(&g_deg[d1.z], 1); atomicAdd(&g_deg[d1.w], 1);
}

// ---------------- scan -------------------------------------------------------
__global__ void k_scanA() {           // per-tile reduction
    __shared__ int wsum[32];
    int b = blockIdx.x, tid = threadIdx.x, lane = tid & 31, w = tid >> 5;
    int i = b * 1024 + tid;
    int v = (i < NN) ? g_deg[i] : 0;
#pragma unroll
    for (int d = 16; d; d >>= 1) v += __shfl_xor_sync(0xffffffffu, v, d);
    if (lane == 0) wsum[w] = v;
    __syncthreads();
    if (w == 0) {
        int t = wsum[lane];
#pragma unroll
        for (int d = 16; d; d >>= 1) t += __shfl_xor_sync(0xffffffffu, t, d);
        if (lane == 0) g_bsum[b] = t;
    }
}

// per-tile scan + (redundant) scan of tile sums for the global offset.
__global__ void k_scanC() {
    __shared__ int wsum[32];
    __shared__ int sboff;
    __shared__ int ws2[2];
    int b = blockIdx.x, tid = threadIdx.x, lane = tid & 31, w = tid >> 5;

    int v2 = 0, x2 = 0;
    if (tid < 64) {
        v2 = (tid < NTILES) ? g_bsum[tid] : 0;
        x2 = v2;
#pragma unroll
        for (int d = 1; d < 32; d <<= 1) {
            int y = __shfl_up_sync(0xffffffffu, x2, d);
            if (lane >= d) x2 += y;
        }
        if (lane == 31) ws2[w] = x2;
    }
    __syncthreads();                       // publish ws2[0] to warp 1
    if (tid >= 32 && tid < 64) x2 += ws2[0];
    if (tid == b) sboff = x2 - v2;         // exclusive offset of this tile
    if (b == 0 && tid == NTILES - 1) g_start[NN] = x2;
    __syncthreads();                       // publish sboff

    int i = b * 1024 + tid;
    int v = (i < NN) ? g_deg[i] : 0;
    int x = v;
#pragma unroll
    for (int d = 1; d < 32; d <<= 1) {
        int y = __shfl_up_sync(0xffffffffu, x, d);
        if (lane >= d) x += y;
    }
    if (lane == 31) wsum[w] = x;
    __syncthreads();
    if (w == 0) {
        int t = wsum[lane];
#pragma unroll
        for (int d = 1; d < 32; d <<= 1) {
            int y = __shfl_up_sync(0xffffffffu, t, d);
            if (lane >= d) t += y;
        }
        wsum[lane] = t;
    }
    __syncthreads();
    int excl = sboff + (w ? wsum[w - 1] : 0) + x - v;
    if (i < NN) { g_start[i] = excl; g_cursor[i] = excl; }
}

// 8 edges per thread, vector loads for MLP.
__global__ void k_scatter(const int* __restrict__ ei, const float* __restrict__ ea) {
    int t = blockIdx.x * blockDim.x + threadIdx.x;
    int e = t * 8;
    if (e >= NE) return;
    int4   s0 = *(const int4*)&ei[e];
    int4   s1 = *(const int4*)&ei[e + 4];
    int4   d0 = *(const int4*)&ei[NE + e];
    int4   d1 = *(const int4*)&ei[NE + e + 4];
    float4 a0 = *(const float4*)&ea[e];
    float4 a1 = *(const float4*)&ea[e + 4];
    int p;
    p = atomicAdd(&g_cursor[d0.x], 1); g_edge[p] = make_int2(s0.x, __float_as_int(a0.x));
    p = atomicAdd(&g_cursor[d0.y], 1); g_edge[p] = make_int2(s0.y, __float_as_int(a0.y));
    p = atomicAdd(&g_cursor[d0.z], 1); g_edge[p] = make_int2(s0.z, __float_as_int(a0.z));
    p = atomicAdd(&g_cursor[d0.w], 1); g_edge[p] = make_int2(s0.w, __float_as_int(a0.w));
    p = atomicAdd(&g_cursor[d1.x], 1); g_edge[p] = make_int2(s1.x, __float_as_int(a1.x));
    p = atomicAdd(&g_cursor[d1.y], 1); g_edge[p] = make_int2(s1.y, __float_as_int(a1.y));
    p = atomicAdd(&g_cursor[d1.z], 1); g_edge[p] = make_int2(s1.z, __float_as_int(a1.z));
    p = atomicAdd(&g_cursor[d1.w], 1); g_edge[p] = make_int2(s1.w, __float_as_int(a1.w));
}

// ---------------- register-blocked linear (layer 1 only) ---------------------
template<int D>
__global__ void __launch_bounds__(256) k_linear(const float* __restrict__ Xext,
                                                const float* __restrict__ W,
                                                const float* __restrict__ as_,
                                                const float* __restrict__ ad_) {
    __shared__ float Wsh[D * 64];
    __shared__ float Xsh[128 * D];
    const float* X = Xext;
    int tid = threadIdx.x;
    int cg = tid & 7, ng = tid >> 3;
    int c0 = cg * 8;
    int h = cg >> 1;

    for (int i = tid * 4; i < D * 64; i += 1024)
        *(float4*)&Wsh[i] = *(const float4*)&W[i];

    int n0 = blockIdx.x * 128;
    int cnt = NN - n0; if (cnt > 128) cnt = 128;
    for (int i = tid * 4; i < cnt * D; i += 1024)
        *(float4*)&Xsh[i] = *(const float4*)&X[n0 * D + i];
    __syncthreads();

    float acc[4][8];
#pragma unroll
    for (int i = 0; i < 4; i++)
#pragma unroll
        for (int j = 0; j < 8; j++) acc[i][j] = 0.f;

#pragma unroll 2
    for (int k = 0; k < D; k++) {
        float4 wlo = *(const float4*)&Wsh[k * 64 + c0];
        float4 whi = *(const float4*)&Wsh[k * 64 + c0 + 4];
        float wr[8] = {wlo.x, wlo.y, wlo.z, wlo.w, whi.x, whi.y, whi.z, whi.w};
#pragma unroll
        for (int i = 0; i < 4; i++) {
            float xv = Xsh[(ng * 4 + i) * D + k];
#pragma unroll
            for (int j = 0; j < 8; j++)
                acc[i][j] = fmaf(xv, wr[j], acc[i][j]);
        }
    }

    float asv[8], adv[8];
#pragma unroll
    for (int j = 0; j < 8; j++) { asv[j] = as_[c0 + j]; adv[j] = ad_[c0 + j]; }

#pragma unroll
    for (int i = 0; i < 4; i++) {
        int node = n0 + ng * 4 + i;
        float ps = 0.f, pd = 0.f;
#pragma unroll
        for (int j = 0; j < 8; j++) {
            ps = fmaf(acc[i][j], asv[j], ps);
            pd = fmaf(acc[i][j], adv[j], pd);
        }
        ps += __shfl_xor_sync(0xffffffffu, ps, 1);
        pd += __shfl_xor_sync(0xffffffffu, pd, 1);
        if (node < NN) {
            float4 lo = make_float4(acc[i][0], acc[i][1], acc[i][2], acc[i][3]);
            float4 hi = make_float4(acc[i][4], acc[i][5], acc[i][6], acc[i][7]);
            *(float4*)&g_xs[node * HCD + c0] = lo;
            *(float4*)&g_xs[node * HCD + c0 + 4] = hi;
            if ((cg & 1) == 0) {
                g_asrc[node * 4 + h] = ps;
                g_adst[node * 4 + h] = pd;
            }
        }
    }
}

// ---------------- half-warp edge aggregation core (macro-free inline) --------
// Lanes 0-15 process even edges, 16-31 odd; each lane owns 4 channels (float4).
// After the xor(16) combine, ALL lanes hold the full msg sums + denominator.
__device__ __forceinline__ void edge_aggregate(
    const float* __restrict__ xs, const float* __restrict__ asrc,
    float adh, float cfh, int s0, int s1, int half, int h, int c0,
    float4& acc, float& dsum)
{
    acc = make_float4(0.f, 0.f, 0.f, 0.f);
    dsum = 0.f;
    int j = s0;
    if (j < s1 && (j & 1)) {            // peel to even for aligned int4 loads
        if (half == 0) {
            int2 ep = g_edge[j];
            float sh = asrc[ep.x * 4 + h];
            float4 xv = *(const float4*)&xs[ep.x * HCD + c0];
            float t = sh + adh + cfh * __int_as_float(ep.y);
            t = t > 0.f ? t : 0.2f * t;
            float w = __expf(t);
            dsum += w;
            acc.x = fmaf(w, xv.x, acc.x); acc.y = fmaf(w, xv.y, acc.y);
            acc.z = fmaf(w, xv.z, acc.z); acc.w = fmaf(w, xv.w, acc.w);
        }
        ++j;
    }
    for (; j + 3 < s1; j += 4) {
        int4 eA = *(const int4*)&g_edge[j];
        int4 eB = *(const int4*)&g_edge[j + 2];
        int  srcA = half ? eA.z : eA.x;
        int  srcB = half ? eB.z : eB.x;
        float aA = __int_as_float(half ? eA.w : eA.y);
        float aB = __int_as_float(half ? eB.w : eB.y);
        float shA = asrc[srcA * 4 + h];
        float shB = asrc[srcB * 4 + h];
        float4 xA = *(const float4*)&xs[srcA * HCD + c0];
        float4 xB = *(const float4*)&xs[srcB * HCD + c0];
        float tA = shA + adh + cfh * aA;
        float tB = shB + adh + cfh * aB;
        tA = tA > 0.f ? tA : 0.2f * tA;
        tB = tB > 0.f ? tB : 0.2f * tB;
        float wA = __expf(tA), wB = __expf(tB);
        dsum += wA + wB;
        acc.x = fmaf(wA, xA.x, acc.x); acc.y = fmaf(wA, xA.y, acc.y);
        acc.z = fmaf(wA, xA.z, acc.z); acc.w = fmaf(wA, xA.w, acc.w);
        acc.x = fmaf(wB, xB.x, acc.x); acc.y = fmaf(wB, xB.y, acc.y);
        acc.z = fmaf(wB, xB.z, acc.z); acc.w = fmaf(wB, xB.w, acc.w);
    }
    if (j + 1 < s1) {
        int4 eA = *(const int4*)&g_edge[j];
        int  src = half ? eA.z : eA.x;
        float a = __int_as_float(half ? eA.w : eA.y);
        float sh = asrc[src * 4 + h];
        float4 xv = *(const float4*)&xs[src * HCD + c0];
        float t = sh + adh + cfh * a;
        t = t > 0.f ? t : 0.2f * t;
        float w = __expf(t);
        dsum += w;
        acc.x = fmaf(w, xv.x, acc.x); acc.y = fmaf(w, xv.y, acc.y);
        acc.z = fmaf(w, xv.z, acc.z); acc.w = fmaf(w, xv.w, acc.w);
        j += 2;
    }
    if (j < s1 && half == 0) {          // single tail edge
        int2 ep = g_edge[j];
        float sh = asrc[ep.x * 4 + h];
        float4 xv = *(const float4*)&xs[ep.x * HCD + c0];
        float t = sh + adh + cfh * __int_as_float(ep.y);
        t = t > 0.f ? t : 0.2f * t;
        float w = __expf(t);
        dsum += w;
        acc.x = fmaf(w, xv.x, acc.x); acc.y = fmaf(w, xv.y, acc.y);
        acc.z = fmaf(w, xv.z, acc.z); acc.w = fmaf(w, xv.w, acc.w);
    }
    // combine halves — all lanes end with the full sums
    dsum  += __shfl_xor_sync(0xffffffffu, dsum, 16);
    acc.x += __shfl_xor_sync(0xffffffffu, acc.x, 16);
    acc.y += __shfl_xor_sync(0xffffffffu, acc.y, 16);
    acc.z += __shfl_xor_sync(0xffffffffu, acc.z, 16);
    acc.w += __shfl_xor_sync(0xffffffffu, acc.w, 16);
}

// ---------------- layer-1 edge aggregation FUSED with layer-2 linear ---------
// h1 never hits global memory: per-warp smem bounce + in-warp 64x64 matvec.
__global__ void __launch_bounds__(512) k_edge_lin(
    const float* __restrict__ b1, const float* __restrict__ W2,
    const float* __restrict__ as2, const float* __restrict__ ad2)
{
    __shared__ float W2s[64 * 64];        // 16 KB
    __shared__ float h1s[16 * 64];        // 4 KB (one row per warp)
    int tid = threadIdx.x;
    for (int i = tid * 4; i < 64 * 64; i += 512 * 4)
        *(float4*)&W2s[i] = *(const float4*)&W2[i];
    __syncthreads();

    int gw = (blockIdx.x * 512 + tid) >> 5;   // 16 warps/block, 3125 blocks
    if (gw >= NN) return;
    int wid = (tid >> 5) & 15;
    int lane = tid & 31;
    int half = lane >> 4, l16 = lane & 15;
    int c0 = l16 * 4, h = l16 >> 2;
    int s0 = g_start[gw], s1 = g_start[gw + 1];

    float adh = g_adst[gw * 4 + h];
    float cfh = g_ce[h];

    float4 acc; float dsum;
    edge_aggregate(g_xs, g_asrc, adh, cfh, s0, s1, half, h, c0, acc, dsum);

    // h1 row (bias + relu), bounce through smem
    float rcp = (dsum > 0.f) ? (1.f / dsum) : 0.f;
    float4 bv = *(const float4*)&b1[c0];
    float4 hv;
    hv.x = fmaxf(acc.x * rcp + bv.x, 0.f);
    hv.y = fmaxf(acc.y * rcp + bv.y, 0.f);
    hv.z = fmaxf(acc.z * rcp + bv.z, 0.f);
    hv.w = fmaxf(acc.w * rcp + bv.w, 0.f);
    float* hw = &h1s[wid * 64];
    if (half == 0) *(float4*)&hw[c0] = hv;
    __syncwarp();

    // xs2 = h1 @ W2 : 4 output channels per lane, k-sum split across halves
    float4 o = make_float4(0.f, 0.f, 0.f, 0.f);
    int kb = half * 32;
#pragma unroll 8
    for (int k = kb; k < kb + 32; k++) {
        float hk = hw[k];
        float4 wv = *(const float4*)&W2s[k * 64 + c0];
        o.x = fmaf(hk, wv.x, o.x); o.y = fmaf(hk, wv.y, o.y);
        o.z = fmaf(hk, wv.z, o.z); o.w = fmaf(hk, wv.w, o.w);
    }
    o.x += __shfl_xor_sync(0xffffffffu, o.x, 16);
    o.y += __shfl_xor_sync(0xffffffffu, o.y, 16);
    o.z += __shfl_xor_sync(0xffffffffu, o.z, 16);
    o.w += __shfl_xor_sync(0xffffffffu, o.w, 16);

    // layer-2 attention head dots (16 channels per head = 4 lanes x 4 ch)
    float4 av = *(const float4*)&as2[c0];
    float4 dv = *(const float4*)&ad2[c0];
    float ps = o.x * av.x + o.y * av.y + o.z * av.z + o.w * av.w;
    float pd = o.x * dv.x + o.y * dv.y + o.z * dv.z + o.w * dv.w;
    ps += __shfl_xor_sync(0xffffffffu, ps, 1);
    ps += __shfl_xor_sync(0xffffffffu, ps, 2);
    pd += __shfl_xor_sync(0xffffffffu, pd, 1);
    pd += __shfl_xor_sync(0xffffffffu, pd, 2);

    if (half == 0) {
        *(float4*)&g_xs2[gw * HCD + c0] = o;
        if ((l16 & 3) == 0) {
            g_asrc2[gw * 4 + h] = ps;
            g_adst2[gw * 4 + h] = pd;
        }
    }
}

// ---------------- layer-2 edge aggregation -----------------------------------
__global__ void k_edge2(const float* __restrict__ bias) {
    int gw = (blockIdx.x * blockDim.x + threadIdx.x) >> 5;
    if (gw >= NN) return;
    int lane = threadIdx.x & 31;
    int half = lane >> 4, l16 = lane & 15;
    int c0 = l16 * 4, h = l16 >> 2;
    int s0 = g_start[gw], s1 = g_start[gw + 1];

    float adh = g_adst2[gw * 4 + h];
    float cfh = g_ce[4 + h];

    float4 acc; float dsum;
    edge_aggregate(g_xs2, g_asrc2, adh, cfh, s0, s1, half, h, c0, acc, dsum);

    if (half == 0) {
        float rcp = (dsum > 0.f) ? (1.f / dsum) : 0.f;
        float4 bv = *(const float4*)&bias[c0];
        float4 ov;
        ov.x = acc.x * rcp + bv.x;
        ov.y = acc.y * rcp + bv.y;
        ov.z = acc.z * rcp + bv.z;
        ov.w = acc.w * rcp + bv.w;
        *(float4*)&g_acc[gw * HCD + c0] = ov;
    }
}

// ---------------- pool (batch is sorted -> segment mean per graph) -----------
__device__ __forceinline__ int lowerb(const int* a, int n, int key) {
    int lo = 0, hi = n;
    while (lo < hi) { int m = (lo + hi) >> 1; if (a[m] < key) lo = m + 1; else hi = m; }
    return lo;
}

__global__ void k_pool(const int* __restrict__ batch, float* __restrict__ out) {
    int g = blockIdx.x;
    int lo = lowerb(batch, NN, g);
    int hi = lowerb(batch, NN, g + 1);
    int tid = threadIdx.x;             // 256
    int c = tid & 63, s = tid >> 6;    // 4 slices
    float acc = 0.f;
    for (int n = lo + s; n < hi; n += 4) acc += g_acc[n * HCD + c];
    __shared__ float sh[256];
    sh[tid] = acc;
    __syncthreads();
    if (s == 0) {
        float v = sh[c] + sh[c + 64] + sh[c + 128] + sh[c + 192];
        float cnt = (float)(hi - lo);
        out[g * HCD + c] = v / fmaxf(cnt, 1.f);
    }
}

// ---------------- launch -----------------------------------------------------
extern "C" void kernel_launch(void* const* d_in, const int* in_sizes, int n_in,
                              void* d_out, int out_size) {
    const float* x   = (const float*)d_in[0];
    const int*   ei  = (const int*)  d_in[1];
    const float* ea  = (const float*)d_in[2];
    const int*   bat = (const int*)  d_in[3];
    const float* W1  = (const float*)d_in[4];
    const float* We1 = (const float*)d_in[5];
    const float* as1 = (const float*)d_in[6];
    const float* ad1 = (const float*)d_in[7];
    const float* ae1 = (const float*)d_in[8];
    const float* b1  = (const float*)d_in[9];
    const float* W2  = (const float*)d_in[10];
    const float* We2 = (const float*)d_in[11];
    const float* as2 = (const float*)d_in[12];
    const float* ad2 = (const float*)d_in[13];
    const float* ae2 = (const float*)d_in[14];
    const float* b2  = (const float*)d_in[15];
    float* out = (float*)d_out;

    const int E8B = (NE / 8 + 255) / 256;          // 391 (8 edges/thread)
    const int FB  = (NN * 32 + 255) / 256;         // 6250 (one warp per node)
    const int F2B = (NN + 15) / 16;                // 3125 (16 warps/block @512)
    const int LB  = (NN + 127) / 128;              // 391 linear tiles

    int *p_deg;
    cudaGetSymbolAddress((void**)&p_deg, g_deg);

    // Fork a side stream for the CSR build so it overlaps with k_linear<128>.
    cudaStream_t side = 0;
    cudaEvent_t evFork = 0, evJoin = 0;
    bool forked =
        (cudaStreamCreateWithFlags(&side, cudaStreamNonBlocking) == cudaSuccess) &&
        (cudaEventCreateWithFlags(&evFork, cudaEventDisableTiming) == cudaSuccess) &&
        (cudaEventCreateWithFlags(&evJoin, cudaEventDisableTiming) == cudaSuccess);

    cudaStream_t cs = forked ? side : 0;   // CSR stream

    if (forked) {
        cudaEventRecord(evFork, 0);            // fork point on capture stream
        cudaStreamWaitEvent(side, evFork, 0);
    }

    // ---- CSR build (side stream when forked) ----
    cudaMemsetAsync(p_deg, 0, NN * sizeof(int), cs);
    k_hist<<<E8B, 256, 0, cs>>>(ei, We1, ae1, We2, ae2);
    k_scanA<<<NTILES, 1024, 0, cs>>>();
    k_scanC<<<NTILES, 1024, 0, cs>>>();
    k_scatter<<<E8B, 256, 0, cs>>>(ei, ea);

    // ---- layer 1 linear (main stream, concurrent with CSR) ----
    k_linear<128><<<LB, 256>>>(x, W1, as1, ad1);

    if (forked) {
        cudaEventRecord(evJoin, side);         // join CSR chain back
        cudaStreamWaitEvent(0, evJoin, 0);
    }

    // ---- layer-1 aggregation + fused layer-2 linear ----
    k_edge_lin<<<F2B, 512>>>(b1, W2, as2, ad2);

    // ---- layer-2 aggregation ----
    k_edge2<<<FB, 256>>>(b2);

    // ---- pool ----
    k_pool<<<64, 256>>>(bat, out);
}